// round 12
// baseline (speedup 1.0000x reference)
#include <cuda_runtime.h>
#include <math.h>

#define RULES 512
#define FEAT  128
#define RES   5
#define BATCH 2048
#define WARPS_PER_BLOCK 16
#define THREADS (WARPS_PER_BLOCK * 32)          // 512 == RULES
#define BLOCKS  (BATCH / WARPS_PER_BLOCK)       // 128  (single wave, 1 block/SM)
#define PAIRS 8                                 // 16 rules/lane as 8 (A,B) pairs
#define NPAIR (RULES / 2)                       // 256

#define LOG2E 1.4426950408889634f

typedef unsigned long long u64;

__device__ __forceinline__ float ex2f(float v) {
    float r;
    asm("ex2.approx.f32 %0, %1;" : "=f"(r) : "f"(v));
    return r;
}
__device__ __forceinline__ float rcpf(float v) {
    float r;
    asm("rcp.approx.f32 %0, %1;" : "=f"(r) : "f"(v));
    return r;
}
__device__ __forceinline__ u64 pack2(float lo, float hi) {
    u64 r;
    asm("mov.b64 %0, {%1, %2};" : "=l"(r) : "f"(lo), "f"(hi));
    return r;
}
__device__ __forceinline__ void unpack2(u64 v, float& lo, float& hi) {
    asm("mov.b64 {%0, %1}, %2;" : "=f"(lo), "=f"(hi) : "l"(v));
}
__device__ __forceinline__ u64 fma2(u64 a, u64 b, u64 c) {
    u64 r;
    asm("fma.rn.f32x2 %0, %1, %2, %3;" : "=l"(r) : "l"(a), "l"(b), "l"(c));
    return r;
}
__device__ __forceinline__ u64 mul2(u64 a, u64 b) {
    u64 r;
    asm("mul.rn.f32x2 %0, %1, %2;" : "=l"(r) : "l"(a), "l"(b));
    return r;
}

__global__ void __launch_bounds__(THREADS, 1)
fused_kernel(const float* __restrict__ x,
             const float* __restrict__ a,
             const float* __restrict__ bmat,
             const float* __restrict__ r,
             const float* __restrict__ d,
             float* __restrict__ out) {
    // Rule-PAIR packed constants. Pair p = m*32+l covers rules A=m*64+l, B=A+32.
    __shared__ float4 sK4[NPAIR];         // (k0A, k1A, k0B, k1B), log2-domain, 1/5 folded in
    __shared__ float2 sBp[RES][NPAIR];    // per grade j: (belief_j of A, belief_j of B)

    const int t = threadIdx.x;
    const int l = t & 31;
    const int w = t >> 5;
    const int row = blockIdx.x * WARPS_PER_BLOCK + w;

    // Issue ALL global loads first; latency overlaps Sx tree + prep math.
    const float4 xv = *reinterpret_cast<const float4*>(x + row * FEAT + l * 4);
    const float av = a[t];
    const float rv = r[t];
    float bv[RES];
    #pragma unroll
    for (int j = 0; j < RES; j++) bv[j] = bmat[t * RES + j];
    const float ed = __expf(d[0]);

    // ---- Sx over raw features (1/5 scale folded into K1); hides prep LDG latency
    float Sx = (xv.x + xv.y) + (xv.z + xv.w);
    #pragma unroll
    for (int o = 16; o; o >>= 1) Sx += __shfl_xor_sync(0xffffffffu, Sx, o);

    // ---- prep: thread t preps rule t; writes into pair-interleaved layout ----
    {
        const int m     = t >> 6;          // pair group 0..7
        const int which = (t >> 5) & 1;    // A(0) or B(1) within pair
        const int p     = m * 32 + l;      // pair index

        float k1 = 0.4f * ed * av;                  // 2*e^d*a * (1/5)
        float k0 = rv - ed * 128.0f * av * av;      // common-mode term dropped (cancels)
        float* kf = reinterpret_cast<float*>(sK4);
        kf[p * 4 + which * 2 + 0] = k0 * LOG2E;
        kf[p * 4 + which * 2 + 1] = k1 * LOG2E;

        float mx = fmaxf(fmaxf(fmaxf(bv[0], bv[1]), fmaxf(bv[2], bv[3])), bv[4]);
        float sum = 0.f;
        #pragma unroll
        for (int j = 0; j < RES; j++) { bv[j] = ex2f((bv[j] - mx) * LOG2E); sum += bv[j]; }
        float inv = rcpf(sum);
        #pragma unroll
        for (int j = 0; j < RES; j++)
            reinterpret_cast<float*>(&sBp[j][p])[which] = bv[j] * inv;
    }
    __syncthreads();                       // the ONLY block barrier

    // ---- rule activations: 8 pairs, 2 independent accumulation chains ----
    float awA[PAIRS], awB[PAIRS];
    float sp0 = 0.f, sp1 = 0.f;
    #pragma unroll
    for (int m = 0; m < PAIRS; m++) {
        float4 K = sK4[m * 32 + l];
        float a0 = ex2f(fmaf(K.y, Sx, K.x));
        float a1 = ex2f(fmaf(K.w, Sx, K.z));
        awA[m] = a0; awB[m] = a1;
        sp0 += a0; sp1 += a1;
    }
    float spart = sp0 + sp1;
    #pragma unroll
    for (int o = 16; o; o >>= 1) spart += __shfl_xor_sync(0xffffffffu, spart, o);
    const float s = spart;

    // ---- evidential combine: packed f32x2, 5 chains carry (A,B) halves ----
    const u64 ONE2 = pack2(1.0f, 1.0f);
    u64 acc0 = ONE2, acc1 = ONE2, acc2 = ONE2, acc3 = ONE2, acc4 = ONE2;
    #pragma unroll
    for (int m = 0; m < PAIRS; m++) {
        const int p = m * 32 + l;
        float a0 = awA[m], a1 = awB[m];
        float r0 = rcpf(s - a0);
        float r1 = rcpf(s - a1);
        u64 ratio2 = mul2(pack2(a0, a1), pack2(r0, r1));
        u64 b0 = *reinterpret_cast<const u64*>(&sBp[0][p]);
        u64 b1 = *reinterpret_cast<const u64*>(&sBp[1][p]);
        u64 b2 = *reinterpret_cast<const u64*>(&sBp[2][p]);
        u64 b3 = *reinterpret_cast<const u64*>(&sBp[3][p]);
        u64 b4 = *reinterpret_cast<const u64*>(&sBp[4][p]);
        acc0 = mul2(acc0, fma2(ratio2, b0, ONE2));
        acc1 = mul2(acc1, fma2(ratio2, b1, ONE2));
        acc2 = mul2(acc2, fma2(ratio2, b2, ONE2));
        acc3 = mul2(acc3, fma2(ratio2, b3, ONE2));
        acc4 = mul2(acc4, fma2(ratio2, b4, ONE2));
    }
    // merge A/B halves, then 5 independent cross-lane product trees
    float p0, p1, p2, p3, p4, hA, hB;
    unpack2(acc0, hA, hB); p0 = hA * hB;
    unpack2(acc1, hA, hB); p1 = hA * hB;
    unpack2(acc2, hA, hB); p2 = hA * hB;
    unpack2(acc3, hA, hB); p3 = hA * hB;
    unpack2(acc4, hA, hB); p4 = hA * hB;
    #pragma unroll
    for (int o = 16; o; o >>= 1) {
        p0 *= __shfl_xor_sync(0xffffffffu, p0, o);
        p1 *= __shfl_xor_sync(0xffffffffu, p1, o);
        p2 *= __shfl_xor_sync(0xffffffffu, p2, o);
        p3 *= __shfl_xor_sync(0xffffffffu, p3, o);
        p4 *= __shfl_xor_sync(0xffffffffu, p4, o);
    }

    if (l == 0) {
        float b0 = p0 - 1.f, b1 = p1 - 1.f, b2 = p2 - 1.f, b3 = p3 - 1.f, b4 = p4 - 1.f;
        float bsum = b0 + b1 + b2 + b3 + b4;
        float acc = fmaf(b0, -0.5f, 0.f);
        acc = fmaf(b2, 0.5f, acc);
        acc = fmaf(b3, 1.0f, acc);
        acc = fmaf(b4, 1.5f, acc);
        out[row] = __fdividef(acc, bsum);
    }
}

extern "C" void kernel_launch(void* const* d_in, const int* in_sizes, int n_in,
                              void* d_out, int out_size) {
    const float* x = (const float*)d_in[0];
    const float* a = (const float*)d_in[1];
    const float* b = (const float*)d_in[2];
    const float* r = (const float*)d_in[3];
    const float* d = (const float*)d_in[4];
    float* out = (float*)d_out;

    fused_kernel<<<BLOCKS, THREADS>>>(x, a, b, r, d, out);
}